// round 16
// baseline (speedup 1.0000x reference)
#include <cuda_runtime.h>
#include <math.h>

#define BATCH 512
#define HO 31
#define WO 31
#define HW 64
#define PLANE (HO * WO)          // 961
#define OUTB (12 * PLANE)        // 11532

// Closed-form reduction (verified R1..R15):
//   per patch: S2=sum p_i^2 ; D2 signed sum (rows +,-,+,-; cols +,-,-,+)
//   dP = pairs rows 0<->3 and 1<->2, same column
//   out[plane] = cA[plane]*(D2/S2) + cB[plane]*(dP/S2); coefs from U3 of qubit 0.
//
// Fused band kernel: block = 8 patch-rows of one image.
//   Phase A: warp w computes patch-row ho=8q+w directly from gmem (R3 body),
//            (Dl,dd) -> 2KB smem.
//   Phase B: per plane p the band's cnt outputs are contiguous; aligned chunks
//            start at a_p=(-p) mod 4 (since 961p+a_p=0 mod 4, and the band base
//            b*11532+248q = 0 mod 4) -> every wide store is an aligned STG.128,
//            issued with __stcs (streaming; output never re-read).

__global__ __launch_bounds__(256) void qconv_fused(const float* __restrict__ x,
                                                   const float* __restrict__ w,
                                                   float* __restrict__ out) {
    __shared__ float2 res2[248];
    __shared__ float cA[12], cB[12];

    const int tid = threadIdx.x;
    const int wq = tid >> 5;
    const int lane = tid & 31;
    const int q = blockIdx.x;                 // band 0..3
    const int b = blockIdx.y;
    const int rows = (q < 3) ? 8 : 7;         // patch rows in band (HO=31)
    const int cnt = rows * WO;                // 248 or 217

    if (tid < 4) {
        const int k = tid;
        float th = w[k * 12 + 0], ph = w[k * 12 + 1], om = w[k * 12 + 2];
        float st, ct, spo, cpo, smp, cmp, sp, cp, som, com_;
        sincosf(th, &st, &ct);
        sincosf(ph, &sp, &cp);
        sincosf(ph + om, &spo, &cpo);
        sincosf(om - ph, &smp, &cmp);
        sincosf(om, &som, &com_);
        float cc = 0.5f * (1.0f + ct);
        float ss = 0.5f * (1.0f - ct);
        cA[3 * k + 0] = st * cp;                         // ex
        cB[3 * k + 0] = 2.0f * (cc * cpo - ss * cmp);
        cA[3 * k + 1] = st * sp;                         // ey
        cB[3 * k + 1] = 2.0f * (cc * spo + ss * smp);
        cA[3 * k + 2] = ct;                              // ez
        cB[3 * k + 2] = -2.0f * st * com_;
    }

    // ---- phase A: one patch per lane, direct from gmem (proven R3 body) ----
    const int ho = 8 * q + wq;
    if (wq < rows && lane < WO) {
        const float* base = x + (size_t)b * (HW * HW) + (size_t)(2 * ho) * HW + 2 * lane;

        float2 u0 = *reinterpret_cast<const float2*>(base);
        float2 v0 = *reinterpret_cast<const float2*>(base + 2);
        float2 u1 = *reinterpret_cast<const float2*>(base + HW);
        float2 v1 = *reinterpret_cast<const float2*>(base + HW + 2);
        float2 u2 = *reinterpret_cast<const float2*>(base + 2 * HW);
        float2 v2 = *reinterpret_cast<const float2*>(base + 2 * HW + 2);
        float2 u3 = *reinterpret_cast<const float2*>(base + 3 * HW);
        float2 v3 = *reinterpret_cast<const float2*>(base + 3 * HW + 2);

        float s0 = u0.x * u0.x + u0.y * u0.y + v0.x * v0.x + v0.y * v0.y;
        float s1 = u1.x * u1.x + u1.y * u1.y + v1.x * v1.x + v1.y * v1.y;
        float s2 = u2.x * u2.x + u2.y * u2.y + v2.x * v2.x + v2.y * v2.y;
        float s3 = u3.x * u3.x + u3.y * u3.y + v3.x * v3.x + v3.y * v3.y;
        float d0 = u0.x * u0.x - u0.y * u0.y - v0.x * v0.x + v0.y * v0.y;
        float d1 = u1.x * u1.x - u1.y * u1.y - v1.x * v1.x + v1.y * v1.y;
        float d2 = u2.x * u2.x - u2.y * u2.y - v2.x * v2.x + v2.y * v2.y;
        float d3 = u3.x * u3.x - u3.y * u3.y - v3.x * v3.x + v3.y * v3.y;
        float S = s0 + s1 + s2 + s3;
        float D = d0 - d1 + d2 - d3;                      // row signs (+,-,+,-)
        float P = u0.x * u3.x + u0.y * u3.y + v0.x * v3.x + v0.y * v3.y
                + u1.x * u2.x + u1.y * u2.y + v1.x * v2.x + v1.y * v2.y;
        float inv = 1.0f / S;                             // reference eps cancels
        res2[wq * WO + lane] = make_float2(D * inv, P * inv);
    }
    __syncthreads();

    // ---- phase B: expansion; 12 planes x 64 slots = 3 iters of 256 threads ----
    const size_t g0 = (size_t)b * OUTB + 248 * q;         // band base (mod 4 == 0)
#pragma unroll
    for (int it = 0; it < 3; ++it) {
        int s = tid + it * 256;                           // 0..767
        int p = s >> 6;                                   // plane 0..11
        int j = s & 63;                                   // chunk slot
        int ap = (4 - (p & 3)) & 3;                       // (-p) mod 4
        int nch = (cnt - ap) >> 2;                        // full chunks (<=62)
        float a = cA[p], g = cB[p];
        float* op = out + g0 + (size_t)p * PLANE;
        if (j < nch) {
            int e = ap + 4 * j;
            float2 r0 = res2[e + 0];
            float2 r1 = res2[e + 1];
            float2 r2 = res2[e + 2];
            float2 r3 = res2[e + 3];
            float4 o = make_float4(a * r0.x + g * r0.y, a * r1.x + g * r1.y,
                                   a * r2.x + g * r2.y, a * r3.x + g * r3.y);
            __stcs(reinterpret_cast<float4*>(op + e), o); // aligned STG.128
        } else if (j == 63) {                             // head + tail scalars
            for (int e = 0; e < ap; ++e) {
                float2 r = res2[e];
                op[e] = a * r.x + g * r.y;
            }
            for (int e = ap + 4 * nch; e < cnt; ++e) {
                float2 r = res2[e];
                op[e] = a * r.x + g * r.y;
            }
        }
    }
}

extern "C" void kernel_launch(void* const* d_in, const int* in_sizes, int n_in,
                              void* d_out, int out_size) {
    const float* x = (const float*)d_in[0];
    const float* w = (const float*)d_in[1];
    if (n_in >= 2 && in_sizes[0] == 48) {  // robustness: weights listed first
        x = (const float*)d_in[1];
        w = (const float*)d_in[0];
    }
    float* out = (float*)d_out;

    dim3 grd(4, BATCH, 1);                  // 4 bands x 512 images
    qconv_fused<<<grd, 256>>>(x, w, out);
}